// round 9
// baseline (speedup 1.0000x reference)
#include <cuda_runtime.h>
#include <cuda_bf16.h>
#include <cstdint>

// Problem constants (fixed by setup_inputs)
#define BATCH 2
#define LSEQ  2048
#define DMODEL 1024
#define NHEADS 16
#define DH 64
#define ROWS (BATCH * LSEQ)          // 4096
#define QKVC (3 * DMODEL)            // 3072
#define QT   64                      // queries per attention CTA
#define KT   192                     // keys per attention CTA (64 + 128)
#define KROW 68                      // padded K/V smem row stride (floats)
#define PROW 196                     // Ps row stride (floats); parts at +49 each

#define K3   (3 * DMODEL)            // bf16-split concatenated K = 3072
#define BK   32                      // bf16 k per smem tile
#define NKT3 (K3 / BK)               // 96 k-tiles
#define SMROW 80                     // padded smem row bytes (64B data + 16B pad)
#define STAGE_BYTES (128 * SMROW)    // 10240 B per matrix per stage
#define GEMM_SMEM (3 * 2 * STAGE_BYTES)            // 61440 B
#define ATTN_SMEM ((KT * KROW + QT * PROW) * 4)    // 102400 B

// ---------------------------------------------------------------------------
// Scratch (device globals; no allocation at runtime)
// ---------------------------------------------------------------------------
__device__ float          g_qkv   [ROWS * QKVC];     // fp32 qkv (48 MB)
__device__ __nv_bfloat16  g_xnb   [ROWS * K3];       // xn split [hi|hi|lo]
__device__ __nv_bfloat16  g_attb  [ROWS * K3];       // att split [hi|hi|lo]
__device__ __nv_bfloat16  g_wqkvb [QKVC * K3];       // w_qkv split [hi|lo|hi]
__device__ __nv_bfloat16  g_woutb [DMODEL * K3];     // w_out split [hi|lo|hi]

// ---------------------------------------------------------------------------
// Baseline-ISA helpers (sm_80-class only: cp.async, ldmatrix, mma.sync)
// ---------------------------------------------------------------------------
__device__ __forceinline__ uint32_t smem_u32(const void* p) {
    uint32_t a;
    asm("{ .reg .u64 t; cvta.to.shared.u64 t, %1; cvt.u32.u64 %0, t; }"
        : "=r"(a) : "l"(p));
    return a;
}
__device__ __forceinline__ void cp16(uint32_t s, const void* g) {
    asm volatile("cp.async.cg.shared.global [%0], [%1], 16;"
                 :: "r"(s), "l"(g) : "memory");
}
#define CP_COMMIT() asm volatile("cp.async.commit_group;" ::: "memory")
#define CP_WAIT(n)  asm volatile("cp.async.wait_group %0;" :: "n"(n) : "memory")

__device__ __forceinline__ void ldmx4(uint32_t* r, uint32_t addr) {
    asm volatile("ldmatrix.sync.aligned.m8n8.x4.shared.b16 {%0,%1,%2,%3}, [%4];"
                 : "=r"(r[0]), "=r"(r[1]), "=r"(r[2]), "=r"(r[3]) : "r"(addr));
}
__device__ __forceinline__ void mma16816(float* d, const uint32_t* a,
                                         uint32_t b0, uint32_t b1) {
    asm volatile(
        "mma.sync.aligned.m16n8k16.row.col.f32.bf16.bf16.f32 "
        "{%0,%1,%2,%3}, {%4,%5,%6,%7}, {%8,%9}, {%0,%1,%2,%3};"
        : "+f"(d[0]), "+f"(d[1]), "+f"(d[2]), "+f"(d[3])
        : "r"(a[0]), "r"(a[1]), "r"(a[2]), "r"(a[3]), "r"(b0), "r"(b1));
}

// ---------------------------------------------------------------------------
// RMSNorm fused with bf16 split: writes [hi|hi|lo] activation layout
// ---------------------------------------------------------------------------
__global__ __launch_bounds__(256) void rmsnorm_split_kernel(
    const float* __restrict__ x, const float* __restrict__ w,
    __nv_bfloat16* __restrict__ xb)
{
    const int row = blockIdx.x;
    const float4* xr = reinterpret_cast<const float4*>(x + (size_t)row * DMODEL);
    float4 v = xr[threadIdx.x];
    float ss = v.x*v.x + v.y*v.y + v.z*v.z + v.w*v.w;

    #pragma unroll
    for (int o = 16; o > 0; o >>= 1)
        ss += __shfl_xor_sync(0xffffffffu, ss, o);

    __shared__ float red[8];
    const int wid = threadIdx.x >> 5, lane = threadIdx.x & 31;
    if (lane == 0) red[wid] = ss;
    __syncthreads();
    if (wid == 0) {
        float t = (lane < 8) ? red[lane] : 0.0f;
        #pragma unroll
        for (int o = 4; o > 0; o >>= 1)
            t += __shfl_xor_sync(0xffffffffu, t, o);
        if (lane == 0) red[0] = rsqrtf(t * (1.0f / DMODEL) + 1e-6f);
    }
    __syncthreads();
    const float s = red[0];
    float4 wv = reinterpret_cast<const float4*>(w)[threadIdx.x];
    float o4[4] = { v.x*s*wv.x, v.y*s*wv.y, v.z*s*wv.z, v.w*s*wv.w };

    __nv_bfloat16 h[4], l[4];
    #pragma unroll
    for (int i = 0; i < 4; i++) {
        h[i] = __float2bfloat16(o4[i]);
        l[i] = __float2bfloat16(o4[i] - __bfloat162float(h[i]));
    }
    __nv_bfloat16* rowb = xb + (size_t)row * K3;
    const int c = threadIdx.x * 4;
    *reinterpret_cast<uint2*>(&rowb[c])              = *reinterpret_cast<uint2*>(h);
    *reinterpret_cast<uint2*>(&rowb[DMODEL + c])     = *reinterpret_cast<uint2*>(h);
    *reinterpret_cast<uint2*>(&rowb[2*DMODEL + c])   = *reinterpret_cast<uint2*>(l);
}

// ---------------------------------------------------------------------------
// Weight split: [hi|lo|hi] layout
// ---------------------------------------------------------------------------
__global__ __launch_bounds__(256) void split_w_kernel(
    const float* __restrict__ W, __nv_bfloat16* __restrict__ Wb, int total)
{
    int i = blockIdx.x * blockDim.x + threadIdx.x;
    if (i >= total) return;
    const int r = i >> 10, c = i & 1023;
    float x = W[i];
    __nv_bfloat16 h = __float2bfloat16(x);
    __nv_bfloat16 l = __float2bfloat16(x - __bfloat162float(h));
    __nv_bfloat16* row = Wb + (size_t)r * K3;
    row[c]              = h;
    row[DMODEL + c]     = l;
    row[2*DMODEL + c]   = h;
}

// ---------------------------------------------------------------------------
// bf16 HMMA GEMM (NT over split-K3): C[m,n] = sum_k3 A[m,k3]*B[n,k3] (+skip)
// 128x128 CTA tile, BK=32, 3-stage cp.async pipeline (dynamic smem),
// 8 warps (warp tile 64x32), mma.sync.m16n8k16 bf16 -> fp32.
// ---------------------------------------------------------------------------
template <bool ADD_SKIP>
__global__ __launch_bounds__(256, 2) void gemm_bf16_mma(
    const __nv_bfloat16* __restrict__ A, const __nv_bfloat16* __restrict__ B,
    const float* __restrict__ skip, float* __restrict__ C, int N)
{
    extern __shared__ __align__(16) char dynsm[];

    const int tid  = threadIdx.x;
    const int warp = tid >> 5, lane = tid & 31;
    const int row0 = blockIdx.y * 128;
    const int col0 = blockIdx.x * 128;
    const int wm = (warp >> 2) * 64;    // 0 or 64
    const int wn = (warp & 3) * 32;     // 0,32,64,96

    const uint32_t sA = smem_u32(dynsm);                     // 3 stages A
    const uint32_t sB = sA + 3 * STAGE_BYTES;                // 3 stages B

    // loader: 512 16B-chunks per matrix per tile; 2 per thread
    const int c0 = tid, c1 = tid + 256;
    const int r0c = c0 >> 2, k0c = (c0 & 3);
    const int r1c = c1 >> 2, k1c = (c1 & 3);
    const __nv_bfloat16* Ag0 = A + (size_t)(row0 + r0c) * K3 + k0c * 8;
    const __nv_bfloat16* Ag1 = A + (size_t)(row0 + r1c) * K3 + k1c * 8;
    const __nv_bfloat16* Bg0 = B + (size_t)(col0 + r0c) * K3 + k0c * 8;
    const __nv_bfloat16* Bg1 = B + (size_t)(col0 + r1c) * K3 + k1c * 8;
    const uint32_t stA0 = sA + r0c * SMROW + k0c * 16;
    const uint32_t stA1 = sA + r1c * SMROW + k1c * 16;
    const uint32_t stB0 = sB + r0c * SMROW + k0c * 16;
    const uint32_t stB1 = sB + r1c * SMROW + k1c * 16;

    float acc[4][4][4];
    #pragma unroll
    for (int i = 0; i < 4; i++)
        #pragma unroll
        for (int j = 0; j < 4; j++)
            #pragma unroll
            for (int f = 0; f < 4; f++) acc[i][j][f] = 0.0f;

    // ldmatrix per-lane address components
    const int arow = lane & 15;                       // A: row within m16
    const int asel = (lane >> 4) * 16;                // A: 0 or 16 bytes (k half)
    const int brow = (lane & 7) + ((lane >> 4) << 3); // B: n within n16
    const int bsel = ((lane >> 3) & 1) * 16;          // B: k half bytes

    // prologue: stages 0,1
    #pragma unroll
    for (int st = 0; st < 2; st++) {
        const uint32_t so = (uint32_t)st * STAGE_BYTES;
        const int ko = st * BK;
        cp16(stA0 + so, Ag0 + ko); cp16(stA1 + so, Ag1 + ko);
        cp16(stB0 + so, Bg0 + ko); cp16(stB1 + so, Bg1 + ko);
        CP_COMMIT();
    }

    int stg = 0;
    for (int kt = 0; kt < NKT3; kt++) {
        if (kt + 2 < NKT3) {
            const uint32_t so = (uint32_t)((kt + 2) % 3) * STAGE_BYTES;
            const int ko = (kt + 2) * BK;
            cp16(stA0 + so, Ag0 + ko); cp16(stA1 + so, Ag1 + ko);
            cp16(stB0 + so, Bg0 + ko); cp16(stB1 + so, Bg1 + ko);
            CP_COMMIT();
            CP_WAIT(2);
        } else if (kt + 1 < NKT3) {
            CP_WAIT(1);
        } else {
            CP_WAIT(0);
        }
        __syncthreads();

        const uint32_t so = (uint32_t)stg * STAGE_BYTES;
        #pragma unroll
        for (int s = 0; s < 2; s++) {          // two k16 steps per BK=32
            uint32_t afr[4][4];
            #pragma unroll
            for (int mt = 0; mt < 4; mt++)
                ldmx4(afr[mt], sA + so + (uint32_t)((wm + mt*16 + arow) * SMROW
                                                    + s*32 + asel));
            uint32_t bfr[2][4];
            #pragma unroll
            for (int nq = 0; nq < 2; nq++)
                ldmx4(bfr[nq], sB + so + (uint32_t)((wn + nq*16 + brow) * SMROW
                                                    + s*32 + bsel));
            #pragma unroll
            for (int mt = 0; mt < 4; mt++)
                #pragma unroll
                for (int nt = 0; nt < 4; nt++)
                    mma16816(acc[mt][nt], afr[mt],
                             bfr[nt >> 1][(nt & 1) * 2],
                             bfr[nt >> 1][(nt & 1) * 2 + 1]);
        }
        __syncthreads();
        stg = (stg + 1) % 3;
    }

    // epilogue: frag layout m16n8: (c0,c1)->row g, cols 2t,2t+1; (c2,c3)->row g+8
    const int er = lane >> 2, ec = (lane & 3) * 2;
    #pragma unroll
    for (int mt = 0; mt < 4; mt++) {
        #pragma unroll
        for (int nt = 0; nt < 4; nt++) {
            const int gr = row0 + wm + mt*16 + er;
            const int gc = col0 + wn + nt*8 + ec;
            float2 v0 = make_float2(acc[mt][nt][0], acc[mt][nt][1]);
            float2 v1 = make_float2(acc[mt][nt][2], acc[mt][nt][3]);
            if (ADD_SKIP) {
                float2 s0 = *reinterpret_cast<const float2*>(skip + (size_t)gr * N + gc);
                float2 s1 = *reinterpret_cast<const float2*>(skip + (size_t)(gr+8) * N + gc);
                v0.x += s0.x; v0.y += s0.y; v1.x += s1.x; v1.y += s1.y;
            }
            *reinterpret_cast<float2*>(C + (size_t)gr * N + gc)     = v0;
            *reinterpret_cast<float2*>(C + (size_t)(gr+8) * N + gc) = v1;
        }
    }
}

// ---------------------------------------------------------------------------
// Banded attention. Grid: (L/QT, H, B), 256 threads, dynamic smem:
//   Ks[192 rows x stride 68] fp32 (K tile, reused for V), Ps[64 x 196].
// 4 threads/query (part = tid&3); part owns keys j = 4*jj + part (interleaved)
// -> the 4 partner rows are consecutive; with the 68-float row stride their
// bank starts differ by 4 words => conflict-free LDS.128 (queries broadcast).
// Epilogue writes bf16-split att [hi|hi|lo].
// ---------------------------------------------------------------------------
__global__ __launch_bounds__(256, 2) void attn_kernel(
    const float* __restrict__ qkv, __nv_bfloat16* __restrict__ attb)
{
    extern __shared__ __align__(16) float asm_[];
    float* Ks = asm_;                 // KT*KROW floats (~51 KB)
    float* Ps = asm_ + KT * KROW;     // QT*PROW floats (~49 KB)

    const int qt = blockIdx.x, h = blockIdx.y, b = blockIdx.z;
    const int q0 = qt * QT;
    const int k0 = q0 - 64;
    const int tid  = threadIdx.x;
    const int part = tid & 3;
    const int q    = tid >> 2;
    const size_t base = (size_t)b * LSEQ * QKVC;
    float* prow = &Ps[q * PROW + part * 49];   // 49: conflict-free part stride

    // ---- K tile (row stride KROW) ----
    for (int idx = tid; idx < KT * (DH/4); idx += 256) {
        const int j = idx >> 4, dc = idx & 15;
        const int kg = k0 + j;
        float4 val = make_float4(0.f, 0.f, 0.f, 0.f);
        if (kg >= 0 && kg < LSEQ)
            val = *reinterpret_cast<const float4*>(
                qkv + base + (size_t)kg * QKVC + DMODEL + h*DH + dc*4);
        *reinterpret_cast<float4*>(&Ks[j*KROW + dc*4]) = val;
    }
    __syncthreads();

    // ---- QK scores -> Ps (masked, scaled); track local max ----
    float mx = -1e30f;
    {
        float qf[DH];
        const float4* qp = reinterpret_cast<const float4*>(
            qkv + base + (size_t)(q0 + q) * QKVC + h*DH);
        #pragma unroll
        for (int dc = 0; dc < 16; dc++) {
            float4 v = qp[dc];
            qf[dc*4+0] = v.x; qf[dc*4+1] = v.y; qf[dc*4+2] = v.z; qf[dc*4+3] = v.w;
        }
        #pragma unroll 4
        for (int jj = 0; jj < 48; jj++) {
            const int j = jj * 4 + part;          // interleaved key ownership
            float s = 0.0f;
            const float4* kp = reinterpret_cast<const float4*>(&Ks[j*KROW]);
            #pragma unroll
            for (int dc = 0; dc < 16; dc++) {
                float4 kv = kp[dc];
                s += qf[dc*4+0]*kv.x + qf[dc*4+1]*kv.y
                   + qf[dc*4+2]*kv.z + qf[dc*4+3]*kv.w;
            }
            s *= 0.125f;
            const int kg = k0 + j;
            const bool valid = (j >= q) && (j <= q + 128) && (kg >= 0) && (kg < LSEQ);
            s = valid ? s : -1e30f;
            prow[jj] = s;
            mx = fmaxf(mx, s);
        }
    }
    mx = fmaxf(mx, __shfl_xor_sync(0xffffffffu, mx, 1));
    mx = fmaxf(mx, __shfl_xor_sync(0xffffffffu, mx, 2));

    // all K reads done -> safe to overwrite Ks with V
    __syncthreads();
    for (int idx = tid; idx < KT * (DH/4); idx += 256) {
        const int j = idx >> 4, dc = idx & 15;
        const int kg = k0 + j;
        float4 val = make_float4(0.f, 0.f, 0.f, 0.f);
        if (kg >= 0 && kg < LSEQ)
            val = *reinterpret_cast<const float4*>(
                qkv + base + (size_t)kg * QKVC + 2*DMODEL + h*DH + dc*4);
        *reinterpret_cast<float4*>(&Ks[j*KROW + dc*4]) = val;
    }

    // exp pass on own Ps entries (no cross-thread deps; overlaps V load)
    float sum = 0.0f;
    #pragma unroll 4
    for (int jj = 0; jj < 48; jj++) {
        const float e = __expf(prow[jj] - mx);
        prow[jj] = e;
        sum += e;
    }
    sum += __shfl_xor_sync(0xffffffffu, sum, 1);
    sum += __shfl_xor_sync(0xffffffffu, sum, 2);
    const float inv = 1.0f / sum;             // self-key always valid => sum > 0
    __syncthreads();                          // V tile complete

    // ---- PV from smem ----
    float acc[DH];
    #pragma unroll
    for (int d = 0; d < DH; d++) acc[d] = 0.0f;
    #pragma unroll 2
    for (int jj = 0; jj < 48; jj++) {
        const float pv = prow[jj];            // e (unnormalized)
        const int j = jj * 4 + part;
        const float4* vp = reinterpret_cast<const float4*>(&Ks[j*KROW]);
        #pragma unroll
        for (int dc = 0; dc < 16; dc++) {
            float4 v = vp[dc];
            acc[dc*4+0] += pv * v.x; acc[dc*4+1] += pv * v.y;
            acc[dc*4+2] += pv * v.z; acc[dc*4+3] += pv * v.w;
        }
    }
    #pragma unroll
    for (int d = 0; d < DH; d++) {
        float r = acc[d] * inv;
        r += __shfl_xor_sync(0xffffffffu, r, 1);
        r += __shfl_xor_sync(0xffffffffu, r, 2);
        acc[d] = r;
    }
    if (part == 0) {
        __nv_bfloat16* rowb = attb + ((size_t)b * LSEQ + q0 + q) * K3;
        #pragma unroll
        for (int dc = 0; dc < 16; dc++) {
            __nv_bfloat16 hh[4], ll[4];
            #pragma unroll
            for (int i = 0; i < 4; i++) {
                const float v = acc[dc*4+i];
                hh[i] = __float2bfloat16(v);
                ll[i] = __float2bfloat16(v - __bfloat162float(hh[i]));
            }
            const int c = h*DH + dc*4;
            *reinterpret_cast<uint2*>(&rowb[c])            = *reinterpret_cast<uint2*>(hh);
            *reinterpret_cast<uint2*>(&rowb[DMODEL + c])   = *reinterpret_cast<uint2*>(hh);
            *reinterpret_cast<uint2*>(&rowb[2*DMODEL + c]) = *reinterpret_cast<uint2*>(ll);
        }
    }
}

// ---------------------------------------------------------------------------
// Launch
// ---------------------------------------------------------------------------
extern "C" void kernel_launch(void* const* d_in, const int* in_sizes, int n_in,
                              void* d_out, int out_size)
{
    const float* x      = (const float*)d_in[0];
    const float* w_norm = (const float*)d_in[1];
    const float* w_qkv  = (const float*)d_in[2];
    const float* w_out  = (const float*)d_in[3];
    float* out = (float*)d_out;

    float *qkv_p;
    __nv_bfloat16 *xnb_p, *attb_p, *wqkvb_p, *woutb_p;
    cudaGetSymbolAddress((void**)&qkv_p,   g_qkv);
    cudaGetSymbolAddress((void**)&xnb_p,   g_xnb);
    cudaGetSymbolAddress((void**)&attb_p,  g_attb);
    cudaGetSymbolAddress((void**)&wqkvb_p, g_wqkvb);
    cudaGetSymbolAddress((void**)&woutb_p, g_woutb);

    // opt-in dynamic smem (host-side attribute set; graph-capture safe)
    cudaFuncSetAttribute(gemm_bf16_mma<false>,
                         cudaFuncAttributeMaxDynamicSharedMemorySize, GEMM_SMEM);
    cudaFuncSetAttribute(gemm_bf16_mma<true>,
                         cudaFuncAttributeMaxDynamicSharedMemorySize, GEMM_SMEM);
    cudaFuncSetAttribute(attn_kernel,
                         cudaFuncAttributeMaxDynamicSharedMemorySize, ATTN_SMEM);

    // 1) RMSNorm + bf16 split of activations
    rmsnorm_split_kernel<<<ROWS, 256>>>(x, w_norm, xnb_p);

    // 1b) weight splits
    split_w_kernel<<<(QKVC * DMODEL + 255) / 256, 256>>>(w_qkv, wqkvb_p, QKVC * DMODEL);
    split_w_kernel<<<(DMODEL * DMODEL + 255) / 256, 256>>>(w_out, woutb_p, DMODEL * DMODEL);

    // 2) QKV GEMM (HMMA): [4096,3072] fp32
    {
        dim3 grid(QKVC / 128, ROWS / 128);   // (24, 32)
        gemm_bf16_mma<false><<<grid, 256, GEMM_SMEM>>>(xnb_p, wqkvb_p, nullptr, qkv_p, QKVC);
    }

    // 3) Banded attention (fp32), writes bf16-split att
    {
        dim3 grid(LSEQ / QT, NHEADS, BATCH); // (32, 16, 2)
        attn_kernel<<<grid, 256, ATTN_SMEM>>>(qkv_p, attb_p);
    }

    // 4) out GEMM (HMMA) + skip: [4096,1024] fp32
    {
        dim3 grid(DMODEL / 128, ROWS / 128); // (8, 32)
        gemm_bf16_mma<true><<<grid, 256, GEMM_SMEM>>>(attb_p, woutb_p, x, out, DMODEL);
    }
}